// round 1
// baseline (speedup 1.0000x reference)
#include <cuda_runtime.h>
#include <math.h>

// ---------------- problem constants ----------------
#define TT 128          // timesteps
#define FF 64           // input features
#define H1V 32          // layer1 hidden
#define G1 128          // 4*H1
#define XH1 96          // FF + H1
#define S1 8            // samples per warp, layer1
#define WARPS1 8

#define H2V 16          // layer2 hidden
#define G2 64           // 4*H2
#define XH2 80          // 64 + H2
#define S2 8            // samples per warp, layer2 (4 per half-warp)
#define WARPS2 8

#define MAXB 4096

// ---------------- scratch (no cudaMalloc allowed) ----------------
__device__ float g_h1[(size_t)MAXB * TT * 64];  // layer1 bidi output [B][T][64]
__device__ float g_h2[MAXB * 32];               // layer2 concat [B][32]

// ---------------- activations ----------------
__device__ __forceinline__ float sigf(float x) {
    return 1.0f / (1.0f + __expf(-x));
}
__device__ __forceinline__ float tanh_f(float x) {
    // 1 - 2/(exp(2x)+1); robust at +-inf, ~1e-7 rel err
    return 1.0f - 2.0f / (__expf(2.0f * x) + 1.0f);
}

// ================= layer 1: bidirectional LSTM, H=32, return sequences ================
// grid: (B/64, 2), block 256. dir = blockIdx.y (0 fwd, 1 bwd).
// Each warp owns S1=8 samples. Lane j owns gate element j (of 32) for all 4 gates.
__global__ void __launch_bounds__(256) lstm1_kernel(
    const float* __restrict__ x,
    const float* __restrict__ Wf, const float* __restrict__ Uf, const float* __restrict__ bf,
    const float* __restrict__ Wb, const float* __restrict__ Ub, const float* __restrict__ bb)
{
    extern __shared__ float smem[];
    float* sW  = smem;                 // [XH1][G1] as [k][elem][gate] -> 48KB
    float* sXH = smem + XH1 * G1;      // [WARPS1][S1][XH1]           -> 24KB

    const int dir = blockIdx.y;
    const float* W    = dir ? Wb : Wf;
    const float* U    = dir ? Ub : Uf;
    const float* bias = dir ? bb : bf;

    const int tid = threadIdx.x;
    const int wrp = tid >> 5;
    const int j   = tid & 31;

    // stage combined [W;U] transposed: sW[k*G1 + elem*4 + gate] = src[k][gate*H1+elem]
    for (int idx = tid; idx < XH1 * G1; idx += blockDim.x) {
        int k = idx / G1;
        int c = idx - k * G1;
        int ee = c >> 2, g = c & 3;
        sW[idx] = (k < FF) ? W[k * G1 + g * H1V + ee]
                           : U[(k - FF) * G1 + g * H1V + ee];
    }
    __syncthreads();

    float bz[4];
    #pragma unroll
    for (int g = 0; g < 4; g++) bz[g] = bias[g * H1V + j];

    const int sampleBase = (blockIdx.x * WARPS1 + wrp) * S1;
    float* xh = sXH + (wrp * S1) * XH1;

    float c_[S1];
    #pragma unroll
    for (int s = 0; s < S1; s++) {
        c_[s] = 0.0f;
        xh[s * XH1 + FF + j] = 0.0f;   // h = 0
    }
    __syncwarp();

    for (int t = 0; t < TT; t++) {
        const int tt = dir ? (TT - 1 - t) : t;

        // stage x_t for 8 samples: 8 * 16 float4 = 128 float4, 4 per lane
        #pragma unroll
        for (int r = 0; r < 4; r++) {
            int fl = j + r * 32;
            int s = fl >> 4, vec = fl & 15;
            const float4 v = *((const float4*)(x + ((size_t)(sampleBase + s) * TT + tt) * FF) + vec);
            *(float4*)&xh[s * XH1 + vec * 4] = v;
        }
        __syncwarp();

        float z[4][S1];
        #pragma unroll
        for (int s = 0; s < S1; s++) {
            z[0][s] = bz[0]; z[1][s] = bz[1]; z[2][s] = bz[2]; z[3][s] = bz[3];
        }

        #pragma unroll 4
        for (int k = 0; k < XH1; k++) {
            const float4 wv = *(const float4*)&sW[k * G1 + j * 4];
            #pragma unroll
            for (int s = 0; s < S1; s++) {
                const float xk = xh[s * XH1 + k];
                z[0][s] = fmaf(wv.x, xk, z[0][s]);
                z[1][s] = fmaf(wv.y, xk, z[1][s]);
                z[2][s] = fmaf(wv.z, xk, z[2][s]);
                z[3][s] = fmaf(wv.w, xk, z[3][s]);
            }
        }

        float hh[S1];
        #pragma unroll
        for (int s = 0; s < S1; s++) {
            const float ig = sigf(z[0][s]);
            const float fg = sigf(z[1][s]);
            const float gg = tanh_f(z[2][s]);
            const float og = sigf(z[3][s]);
            c_[s] = fg * c_[s] + ig * gg;
            hh[s] = og * tanh_f(c_[s]);
        }

        __syncwarp();  // all lanes finished reading old h
        #pragma unroll
        for (int s = 0; s < S1; s++) {
            xh[s * XH1 + FF + j] = hh[s];
            g_h1[((size_t)(sampleBase + s) * TT + tt) * 64 + dir * H1V + j] = hh[s];
        }
        __syncwarp();  // new h visible before next step reads
    }
}

// ================= layer 2: bidirectional LSTM, H=16, return last h ================
// grid: (B/64, 2), block 256. Lane mapping: e = j&15 (gate elem), hw = j>>4 picks
// which 4 of the warp's 8 samples this lane serves.
__global__ void __launch_bounds__(256) lstm2_kernel(
    const float* __restrict__ W2f, const float* __restrict__ U2f, const float* __restrict__ b2f,
    const float* __restrict__ W2b, const float* __restrict__ U2b, const float* __restrict__ b2b)
{
    __shared__ float sW[XH2 * G2];             // 20KB
    __shared__ float sXH[WARPS2 * S2 * XH2];   // 20KB

    const int dir = blockIdx.y;
    const float* W    = dir ? W2b : W2f;
    const float* U    = dir ? U2b : U2f;
    const float* bias = dir ? b2b : b2f;

    const int tid = threadIdx.x;
    const int wrp = tid >> 5;
    const int j   = tid & 31;
    const int e   = j & 15;
    const int hw  = j >> 4;

    for (int idx = tid; idx < XH2 * G2; idx += blockDim.x) {
        int k = idx / G2;
        int c = idx - k * G2;
        int ee = c >> 2, g = c & 3;
        sW[idx] = (k < 64) ? W[k * G2 + g * H2V + ee]
                           : U[(k - 64) * G2 + g * H2V + ee];
    }
    __syncthreads();

    float bz[4];
    #pragma unroll
    for (int g = 0; g < 4; g++) bz[g] = bias[g * H2V + e];

    const int sampleBase = (blockIdx.x * WARPS2 + wrp) * S2;
    float* xh = sXH + (wrp * S2) * XH2;

    float c_[4], hh[4];
    #pragma unroll
    for (int s = 0; s < 4; s++) {
        c_[s] = 0.0f;
        hh[s] = 0.0f;
        xh[(hw * 4 + s) * XH2 + 64 + e] = 0.0f;
    }
    __syncwarp();

    for (int t = 0; t < TT; t++) {
        const int tt = dir ? (TT - 1 - t) : t;

        // stage layer1 output [b][tt][0..63] for 8 samples
        #pragma unroll
        for (int r = 0; r < 4; r++) {
            int fl = j + r * 32;
            int s = fl >> 4, vec = fl & 15;
            const float4 v = *((const float4*)(g_h1 + ((size_t)(sampleBase + s) * TT + tt) * 64) + vec);
            *(float4*)&xh[s * XH2 + vec * 4] = v;
        }
        __syncwarp();

        float z[4][4];
        #pragma unroll
        for (int s = 0; s < 4; s++) {
            z[0][s] = bz[0]; z[1][s] = bz[1]; z[2][s] = bz[2]; z[3][s] = bz[3];
        }

        #pragma unroll 4
        for (int k = 0; k < XH2; k++) {
            const float4 wv = *(const float4*)&sW[k * G2 + e * 4];
            #pragma unroll
            for (int s = 0; s < 4; s++) {
                const float xk = xh[(hw * 4 + s) * XH2 + k];
                z[0][s] = fmaf(wv.x, xk, z[0][s]);
                z[1][s] = fmaf(wv.y, xk, z[1][s]);
                z[2][s] = fmaf(wv.z, xk, z[2][s]);
                z[3][s] = fmaf(wv.w, xk, z[3][s]);
            }
        }

        #pragma unroll
        for (int s = 0; s < 4; s++) {
            const float ig = sigf(z[0][s]);
            const float fg = sigf(z[1][s]);
            const float gg = tanh_f(z[2][s]);
            const float og = sigf(z[3][s]);
            c_[s] = fg * c_[s] + ig * gg;
            hh[s] = og * tanh_f(c_[s]);
        }

        __syncwarp();
        #pragma unroll
        for (int s = 0; s < 4; s++)
            xh[(hw * 4 + s) * XH2 + 64 + e] = hh[s];
        __syncwarp();
    }

    // final h: fwd -> cols [0,16), bwd -> cols [16,32)
    #pragma unroll
    for (int s = 0; s < 4; s++)
        g_h2[(sampleBase + hw * 4 + s) * 32 + dir * H2V + e] = hh[s];
}

// ================= head: dense(8)+swish, dense(2)+sigmoid ================
__global__ void head_kernel(
    const float* __restrict__ W3, const float* __restrict__ b3,
    const float* __restrict__ W4, const float* __restrict__ b4,
    float* __restrict__ out, int B)
{
    const int b = blockIdx.x * blockDim.x + threadIdx.x;
    if (b >= B) return;

    float xv[32];
    #pragma unroll
    for (int i = 0; i < 32; i++) xv[i] = g_h2[b * 32 + i];

    float y[8];
    #pragma unroll
    for (int o = 0; o < 8; o++) {
        float acc = b3[o];
        #pragma unroll
        for (int k = 0; k < 32; k++)
            acc = fmaf(xv[k], W3[k * 8 + o], acc);
        y[o] = acc * sigf(acc);   // swish
    }

    #pragma unroll
    for (int m = 0; m < 2; m++) {
        float acc = b4[m];
        #pragma unroll
        for (int o = 0; o < 8; o++)
            acc = fmaf(y[o], W4[o * 2 + m], acc);
        out[b * 2 + m] = sigf(acc);
    }
}

// ================= launch ================
extern "C" void kernel_launch(void* const* d_in, const int* in_sizes, int n_in,
                              void* d_out, int out_size)
{
    const float* x   = (const float*)d_in[0];
    const float* W1f = (const float*)d_in[1];
    const float* U1f = (const float*)d_in[2];
    const float* b1f = (const float*)d_in[3];
    const float* W1b = (const float*)d_in[4];
    const float* U1b = (const float*)d_in[5];
    const float* b1b = (const float*)d_in[6];
    const float* W2f = (const float*)d_in[7];
    const float* U2f = (const float*)d_in[8];
    const float* b2f = (const float*)d_in[9];
    const float* W2b = (const float*)d_in[10];
    const float* U2b = (const float*)d_in[11];
    const float* b2b = (const float*)d_in[12];
    const float* W3  = (const float*)d_in[13];
    const float* b3  = (const float*)d_in[14];
    const float* W4  = (const float*)d_in[15];
    const float* b4  = (const float*)d_in[16];
    float* out = (float*)d_out;

    const int B = in_sizes[0] / (TT * FF);   // 4096

    const int smem1 = (XH1 * G1 + WARPS1 * S1 * XH1) * (int)sizeof(float);  // 72KB
    cudaFuncSetAttribute(lstm1_kernel, cudaFuncAttributeMaxDynamicSharedMemorySize, smem1);

    lstm1_kernel<<<dim3(B / (WARPS1 * S1), 2), 256, smem1>>>(
        x, W1f, U1f, b1f, W1b, U1b, b1b);

    lstm2_kernel<<<dim3(B / (WARPS2 * S2), 2), 256>>>(
        W2f, U2f, b2f, W2b, U2b, b2b);

    head_kernel<<<(B + 255) / 256, 256>>>(W3, b3, W4, b4, out, B);
}